// round 8
// baseline (speedup 1.0000x reference)
#include <cuda_runtime.h>
#include <cuda_bf16.h>
#include <cstdint>

#define NN 100000
#define NE 1600000

typedef unsigned long long ull;

// ---------------------------------------------------------------------------
// Device scratch (no runtime allocation allowed)
// ---------------------------------------------------------------------------
__device__ float g_SR[(size_t)NN * 256];   // [n][0:128]=S(+b1), [128:256]=R
__device__ float g_deg[NN];                // raw degree (edge kernel accumulates)
__device__ ull   g_W1f[16 * 2 * 2 * 32];   // B1 frags: [j16][t2][term2][lane32]
__device__ ull   g_W2f[8 * 8 * 2 * 32];    // B2 frags: [j8][t8][term2][lane32]

// ---------------------------------------------------------------------------
// helpers
// ---------------------------------------------------------------------------
__device__ __forceinline__ void mma16816(float c[4], const uint32_t a[4],
                                         uint32_t b0, uint32_t b1) {
    asm volatile(
        "mma.sync.aligned.m16n8k16.row.col.f32.bf16.bf16.f32 "
        "{%0,%1,%2,%3},{%4,%5,%6,%7},{%8,%9},{%0,%1,%2,%3};"
        : "+f"(c[0]), "+f"(c[1]), "+f"(c[2]), "+f"(c[3])
        : "r"(a[0]), "r"(a[1]), "r"(a[2]), "r"(a[3]), "r"(b0), "r"(b1));
}

// pack (x -> low half, y -> high half) as bf16x2; also produce residual pack
__device__ __forceinline__ void bfs2(float x, float y, uint32_t& hi, uint32_t& lo) {
    asm("cvt.rn.bf16x2.f32 %0, %1, %2;" : "=r"(hi) : "f"(y), "f"(x));
    float xr = x - __uint_as_float(hi << 16);
    float yr = y - __uint_as_float(hi & 0xFFFF0000u);
    asm("cvt.rn.bf16x2.f32 %0, %1, %2;" : "=r"(lo) : "f"(yr), "f"(xr));
}

// fp32x2 helpers for node-side kernels
__device__ __forceinline__ ull dup2(float x) { ull r; asm("mov.b64 %0,{%1,%1};" : "=l"(r) : "f"(x)); return r; }
__device__ __forceinline__ float2 up2(ull v) { float2 r; asm("mov.b64 {%0,%1},%2;" : "=f"(r.x), "=f"(r.y) : "l"(v)); return r; }
__device__ __forceinline__ ull fma2(ull a, ull b, ull c) { ull d; asm("fma.rn.f32x2 %0,%1,%2,%3;" : "=l"(d) : "l"(a), "l"(b), "l"(c)); return d; }

// ---------------------------------------------------------------------------
// zero kernel: d_out and g_deg
// ---------------------------------------------------------------------------
__global__ void zero_kernel(float* __restrict__ out) {
    int i = blockIdx.x * blockDim.x + threadIdx.x;
    if (i < NN * 64) out[i] = 0.0f;
    if (i < NN) g_deg[i] = 0.0f;
}

// ---------------------------------------------------------------------------
// Weight fragment prep (bf16 hi/lo split, mma B-fragment order)
// ---------------------------------------------------------------------------
__global__ void prep_frags(const float* __restrict__ W1, const float* __restrict__ W2) {
    int idx = blockIdx.x * blockDim.x + threadIdx.x;
    if (idx < 2048) {                        // W1c frags
        int lane = idx & 31, fragid = idx >> 5;
        int term = fragid & 1, t = (fragid >> 1) & 1, j = fragid >> 2;
        int n = j * 8 + (lane >> 2);
        int k0 = t * 16 + (lane & 3) * 2;
        float v00 = W1[(size_t)(128 + k0) * 128 + n];
        float v01 = W1[(size_t)(128 + k0 + 1) * 128 + n];
        float v10 = W1[(size_t)(128 + k0 + 8) * 128 + n];
        float v11 = W1[(size_t)(128 + k0 + 9) * 128 + n];
        uint32_t h0, l0, h1, l1;
        bfs2(v00, v01, h0, l0);
        bfs2(v10, v11, h1, l1);
        g_W1f[idx] = term ? (((ull)l1 << 32) | l0) : (((ull)h1 << 32) | h0);
    }
    if (idx < 4096) {                        // W2 frags
        int lane = idx & 31, fragid = idx >> 5;
        int term = fragid & 1, t = (fragid >> 1) & 7, j = fragid >> 4;
        int n = j * 8 + (lane >> 2);
        int k0 = t * 16 + (lane & 3) * 2;
        float v00 = W2[(size_t)k0 * 64 + n];
        float v01 = W2[(size_t)(k0 + 1) * 64 + n];
        float v10 = W2[(size_t)(k0 + 8) * 64 + n];
        float v11 = W2[(size_t)(k0 + 9) * 64 + n];
        uint32_t h0, l0, h1, l1;
        bfs2(v00, v01, h0, l0);
        bfs2(v10, v11, h1, l1);
        g_W2f[idx] = term ? (((ull)l1 << 32) | l0) : (((ull)h1 << 32) | h0);
    }
}

// ---------------------------------------------------------------------------
// Fused S|R precompute (proven): g_SR = nodes @ [W1a|W1b] (+b1 on S half)
// ---------------------------------------------------------------------------
__global__ void __launch_bounds__(256) sr_gemm_kernel(
    const float* __restrict__ A, const float* __restrict__ W1,
    const float* __restrict__ b1, int M)
{
    extern __shared__ float sm[];
    float* sAT = sm;               // [64][68]
    float* sB  = sm + 64 * 68;     // [64][256]
    const int tid = threadIdx.x;
    const int n0  = blockIdx.x * 64;

#pragma unroll
    for (int j = 0; j < 4; j++) {
        int s = tid + j * 256;
        int row = s >> 4, k0 = (s & 15) << 2, gn = n0 + row;
        float4 v = make_float4(0.f, 0.f, 0.f, 0.f);
        if (gn < M) v = *(const float4*)(A + (size_t)gn * 64 + k0);
        sAT[(k0 + 0) * 68 + row] = v.x; sAT[(k0 + 1) * 68 + row] = v.y;
        sAT[(k0 + 2) * 68 + row] = v.z; sAT[(k0 + 3) * 68 + row] = v.w;
    }
#pragma unroll
    for (int j = 0; j < 16; j++) {
        int s = tid + j * 256;
        int r = s >> 6, c4 = (s & 63) * 4;
        const float* src = (c4 < 128) ? (W1 + (size_t)r * 128 + c4)
                                      : (W1 + (size_t)(64 + r) * 128 + (c4 - 128));
        *(float4*)(sB + r * 256 + c4) = *(const float4*)src;
    }
    __syncthreads();

    const int ty = tid >> 4, tx = tid & 15;
    ull acc[4][4][2];
#pragma unroll
    for (int m = 0; m < 4; m++)
#pragma unroll
        for (int q = 0; q < 4; q++) { acc[m][q][0] = 0ull; acc[m][q][1] = 0ull; }

#pragma unroll 8
    for (int k = 0; k < 64; k++) {
        float4 a = *(const float4*)(sAT + k * 68 + ty * 4);
        ull aa[4] = {dup2(a.x), dup2(a.y), dup2(a.z), dup2(a.w)};
#pragma unroll
        for (int q = 0; q < 4; q++) {
            ulonglong2 b = *(const ulonglong2*)(sB + k * 256 + q * 64 + tx * 4);
#pragma unroll
            for (int m = 0; m < 4; m++) {
                acc[m][q][0] = fma2(aa[m], b.x, acc[m][q][0]);
                acc[m][q][1] = fma2(aa[m], b.y, acc[m][q][1]);
            }
        }
    }
    float4 bq[4];
#pragma unroll
    for (int q = 0; q < 4; q++)
        bq[q] = (q < 2) ? *(const float4*)(b1 + q * 64 + tx * 4)
                        : make_float4(0.f, 0.f, 0.f, 0.f);
#pragma unroll
    for (int m = 0; m < 4; m++) {
        int gn = n0 + ty * 4 + m;
        if (gn < M) {
#pragma unroll
            for (int q = 0; q < 4; q++) {
                float2 u0 = up2(acc[m][q][0]), u1 = up2(acc[m][q][1]);
                *(float4*)(g_SR + (size_t)gn * 256 + q * 64 + tx * 4) =
                    make_float4(u0.x + bq[q].x, u0.y + bq[q].y, u1.x + bq[q].z, u1.y + bq[q].w);
            }
        }
    }
}

// ---------------------------------------------------------------------------
// Final kernel: out = out_agg * 1/max(deg,1) + nodes @ Wn + bn
// ---------------------------------------------------------------------------
__global__ void __launch_bounds__(256) final_kernel(
    const float* __restrict__ A, const float* __restrict__ B,
    const float* __restrict__ bias, float* __restrict__ C, int M)
{
    extern __shared__ float sm[];
    float* sAT = sm;
    float* sB  = sm + 64 * 68;
    const int tid = threadIdx.x;
    const int n0  = blockIdx.x * 64;

#pragma unroll
    for (int j = 0; j < 4; j++) {
        int s = tid + j * 256;
        int row = s >> 4, k0 = (s & 15) << 2, gn = n0 + row;
        float4 v = make_float4(0.f, 0.f, 0.f, 0.f);
        if (gn < M) v = *(const float4*)(A + (size_t)gn * 64 + k0);
        sAT[(k0 + 0) * 68 + row] = v.x; sAT[(k0 + 1) * 68 + row] = v.y;
        sAT[(k0 + 2) * 68 + row] = v.z; sAT[(k0 + 3) * 68 + row] = v.w;
    }
#pragma unroll
    for (int j = 0; j < 4; j++) {
        int s = tid + j * 256;
        ((float4*)sB)[s] = ((const float4*)B)[s];
    }
    __syncthreads();

    const int ty = tid >> 4, tx = tid & 15;
    ull acc[4][2];
#pragma unroll
    for (int m = 0; m < 4; m++) { acc[m][0] = 0ull; acc[m][1] = 0ull; }
#pragma unroll 8
    for (int k = 0; k < 64; k++) {
        float4 a = *(const float4*)(sAT + k * 68 + ty * 4);
        ulonglong2 b = *(const ulonglong2*)(sB + k * 64 + tx * 4);
        ull aa[4] = {dup2(a.x), dup2(a.y), dup2(a.z), dup2(a.w)};
#pragma unroll
        for (int m = 0; m < 4; m++) {
            acc[m][0] = fma2(aa[m], b.x, acc[m][0]);
            acc[m][1] = fma2(aa[m], b.y, acc[m][1]);
        }
    }
    float4 bb = *(const float4*)(bias + tx * 4);
#pragma unroll
    for (int m = 0; m < 4; m++) {
        int gn = n0 + ty * 4 + m;
        if (gn < M) {
            float inv = 1.0f / fmaxf(g_deg[gn], 1.0f);
            float4 ag = *(const float4*)(C + (size_t)gn * 64 + tx * 4);
            float2 u0 = up2(acc[m][0]), u1 = up2(acc[m][1]);
            *(float4*)(C + (size_t)gn * 64 + tx * 4) =
                make_float4(ag.x * inv + u0.x + bb.x, ag.y * inv + u0.y + bb.y,
                            ag.z * inv + u1.x + bb.z, ag.w * inv + u1.y + bb.w);
        }
    }
}

// ---------------------------------------------------------------------------
// Edge kernel: persistent warps, mma.sync bf16x3, register-resident fusion.
// 12 warps/SM (3 blocks x 128 threads). Scatters RAW (m+b2) sums + degree.
// ---------------------------------------------------------------------------
#define N_CHUNKS (NE / 32)

__global__ void __launch_bounds__(128, 3) edge_kernel(
    const float* __restrict__ edges,
    const int*   __restrict__ senders,
    const int*   __restrict__ receivers,
    const float* __restrict__ b2,
    float*       __restrict__ out)
{
    extern __shared__ char smem[];
    ull*   sW1f = (ull*)smem;
    ull*   sW2f = (ull*)(smem + 16384);
    float* sE   = (float*)(smem + 49152);

    const int tid  = threadIdx.x;
    const int w    = tid >> 5;
    const int lane = tid & 31;

    // stage weight fragments once per block
#pragma unroll
    for (int j = 0; j < 16; j++) sW1f[tid + j * 128] = g_W1f[tid + j * 128];
#pragma unroll
    for (int j = 0; j < 32; j++) sW2f[tid + j * 128] = g_W2f[tid + j * 128];
    __syncthreads();

    float* myE = sE + w * 32 * 36;
    const int gw     = blockIdx.x * 4 + w;
    const int stride = gridDim.x * 4;

    const int r   = lane >> 2;          // 0..7
    const int c2x = (lane & 3) * 2;     // 0,2,4,6
    const int pb  = (lane >> 1) & 1;    // pair base selector
    const bool oddl = lane & 1;

    for (int chunk = gw; chunk < N_CHUNKS; chunk += stride) {
        const int e0 = chunk * 32;
        __syncwarp();
#pragma unroll
        for (int q = 0; q < 8; q++) {
            int row = q * 4 + (lane >> 3);
            int col = (lane & 7) * 4;
            *(float4*)(myE + row * 36 + col) =
                *(const float4*)(edges + (size_t)(e0 + row) * 32 + col);
        }
        const int snd = senders[e0 + lane];
        const int rcv = receivers[e0 + lane];
        atomicAdd(&g_deg[rcv], 1.0f);       // no return use -> RED
        __syncwarp();

#pragma unroll
        for (int mt = 0; mt < 2; mt++) {
            const int mb = mt * 16;

            // ---- A1 fragments (edge feats, hi/lo split) ----
            uint32_t a1h[2][4], a1l[2][4];
#pragma unroll
            for (int t = 0; t < 2; t++) {
                float2 x0 = *(const float2*)(myE + (mb + r) * 36 + t * 16 + c2x);
                float2 x1 = *(const float2*)(myE + (mb + r + 8) * 36 + t * 16 + c2x);
                float2 x2 = *(const float2*)(myE + (mb + r) * 36 + t * 16 + c2x + 8);
                float2 x3 = *(const float2*)(myE + (mb + r + 8) * 36 + t * 16 + c2x + 8);
                bfs2(x0.x, x0.y, a1h[t][0], a1l[t][0]);
                bfs2(x1.x, x1.y, a1h[t][1], a1l[t][1]);
                bfs2(x2.x, x2.y, a1h[t][2], a1l[t][2]);
                bfs2(x3.x, x3.y, a1h[t][3], a1l[t][3]);
            }

            const int s_r  = __shfl_sync(0xFFFFFFFFu, snd, mb + r);
            const int s_r8 = __shfl_sync(0xFFFFFFFFu, snd, mb + r + 8);
            const int r_r  = __shfl_sync(0xFFFFFFFFu, rcv, mb + r);
            const int r_r8 = __shfl_sync(0xFFFFFFFFu, rcv, mb + r + 8);
            const float* Sr  = g_SR + (size_t)s_r  * 256;
            const float* Sr8 = g_SR + (size_t)s_r8 * 256;
            const float* Rr  = g_SR + (size_t)r_r  * 256 + 128;
            const float* Rr8 = g_SR + (size_t)r_r8 * 256 + 128;

            // ---- GEMM1 + epilogue1 -> A2 frags ----
            uint32_t a2h[8][4], a2l[8][4];
#pragma unroll
            for (int t2 = 0; t2 < 8; t2++) {
                float c1[2][4] = {{0.f, 0.f, 0.f, 0.f}, {0.f, 0.f, 0.f, 0.f}};
#pragma unroll
                for (int half = 0; half < 2; half++) {
                    int j = t2 * 2 + half;
#pragma unroll
                    for (int t = 0; t < 2; t++) {
                        ull bh = sW1f[((j * 2 + t) * 2 + 0) * 32 + lane];
                        ull bl = sW1f[((j * 2 + t) * 2 + 1) * 32 + lane];
                        uint32_t bh0 = (uint32_t)bh, bh1 = (uint32_t)(bh >> 32);
                        uint32_t bl0 = (uint32_t)bl, bl1 = (uint32_t)(bl >> 32);
                        mma16816(c1[half], a1h[t], bh0, bh1);
                        mma16816(c1[half], a1h[t], bl0, bl1);
                        mma16816(c1[half], a1l[t], bh0, bh1);
                    }
                }
#pragma unroll
                for (int half = 0; half < 2; half++) {
                    int j = t2 * 2 + half;
                    float2 sv0 = *(const float2*)(Sr  + j * 8 + c2x);
                    float2 sv1 = *(const float2*)(Sr8 + j * 8 + c2x);
                    float2 rv0 = *(const float2*)(Rr  + j * 8 + c2x);
                    float2 rv1 = *(const float2*)(Rr8 + j * 8 + c2x);
                    float h0 = fmaxf(c1[half][0] + sv0.x + rv0.x, 0.f);
                    float h1 = fmaxf(c1[half][1] + sv0.y + rv0.y, 0.f);
                    float h2 = fmaxf(c1[half][2] + sv1.x + rv1.x, 0.f);
                    float h3 = fmaxf(c1[half][3] + sv1.y + rv1.y, 0.f);
                    bfs2(h0, h1, a2h[t2][half * 2 + 0], a2l[t2][half * 2 + 0]);
                    bfs2(h2, h3, a2h[t2][half * 2 + 1], a2l[t2][half * 2 + 1]);
                }
            }

            const int er = oddl ? r_r8 : r_r;
            float* outp = out + (size_t)er * 64 + pb * 4;

            // ---- GEMM2 per n-tile + raw scatter ----
#pragma unroll
            for (int j = 0; j < 8; j++) {
                float c2[4] = {0.f, 0.f, 0.f, 0.f};
#pragma unroll
                for (int t = 0; t < 8; t++) {
                    ull bh = sW2f[((j * 8 + t) * 2 + 0) * 32 + lane];
                    ull bl = sW2f[((j * 8 + t) * 2 + 1) * 32 + lane];
                    uint32_t bh0 = (uint32_t)bh, bh1 = (uint32_t)(bh >> 32);
                    uint32_t bl0 = (uint32_t)bl, bl1 = (uint32_t)(bl >> 32);
                    mma16816(c2, a2h[t], bh0, bh1);
                    mma16816(c2, a2h[t], bl0, bl1);
                    mma16816(c2, a2l[t], bh0, bh1);
                }
                float x0 = __shfl_xor_sync(0xFFFFFFFFu, c2[0], 1);
                float x1 = __shfl_xor_sync(0xFFFFFFFFu, c2[1], 1);
                float x2 = __shfl_xor_sync(0xFFFFFFFFu, c2[2], 1);
                float x3 = __shfl_xor_sync(0xFFFFFFFFu, c2[3], 1);
                float v0, v1, v2, v3;
                if (!oddl) { v0 = c2[0]; v1 = c2[1]; v2 = x0; v3 = x1; }
                else       { v0 = x2;    v1 = x3;    v2 = c2[2]; v3 = c2[3]; }
                float4 bb = *(const float4*)(b2 + j * 8 + pb * 4);
                v0 += bb.x;  v1 += bb.y;  v2 += bb.z;  v3 += bb.w;
                asm volatile("red.global.add.v4.f32 [%0], {%1,%2,%3,%4};"
                             :: "l"(outp + j * 8), "f"(v0), "f"(v1), "f"(v2), "f"(v3)
                             : "memory");
            }
        }
    }
}

// ---------------------------------------------------------------------------
// Launch
// ---------------------------------------------------------------------------
extern "C" void kernel_launch(void* const* d_in, const int* in_sizes, int n_in,
                              void* d_out, int out_size)
{
    const float* nodes     = (const float*)d_in[0];
    const float* edges     = (const float*)d_in[1];
    const int*   senders   = (const int*)d_in[2];
    const int*   receivers = (const int*)d_in[3];
    const float* W1        = (const float*)d_in[4];
    const float* b1        = (const float*)d_in[5];
    const float* W2        = (const float*)d_in[6];
    const float* b2        = (const float*)d_in[7];
    const float* Wn        = (const float*)d_in[8];
    const float* bn        = (const float*)d_in[9];
    float* out = (float*)d_out;

    const size_t sm_sr    = (64 * 68 + 64 * 256) * sizeof(float);
    const size_t sm_small = (64 * 68 + 64 * 64) * sizeof(float);
    const size_t sm_edge  = 16384 + 32768 + 4 * 32 * 36 * sizeof(float);  // 67,584

    cudaFuncSetAttribute(sr_gemm_kernel,
                         cudaFuncAttributeMaxDynamicSharedMemorySize, (int)sm_sr);
    cudaFuncSetAttribute(edge_kernel,
                         cudaFuncAttributeMaxDynamicSharedMemorySize, (int)sm_edge);

    zero_kernel<<<(NN * 64 + 255) / 256, 256>>>(out);
    prep_frags<<<16, 256>>>(W1, W2);

    int gnodes = (NN + 63) / 64;
    sr_gemm_kernel<<<gnodes, 256, sm_sr>>>(nodes, W1, b1, NN);

    edge_kernel<<<444, 128, sm_edge>>>(edges, senders, receivers, b2, out);

    final_kernel<<<gnodes, 256, sm_small>>>(nodes, Wn, bn, out, NN);
}

// round 9
// speedup vs baseline: 1.3310x; 1.3310x over previous
#include <cuda_runtime.h>
#include <cuda_bf16.h>
#include <cstdint>

#define NN 100000
#define NE 1600000

typedef unsigned long long ull;

// ---------------------------------------------------------------------------
// Device scratch (no runtime allocation allowed)
// ---------------------------------------------------------------------------
__device__ float g_SR[(size_t)NN * 256];   // [n][0:128]=S(+b1), [128:256]=R
__device__ float g_deg[NN];                // raw degree (edge kernel accumulates)
__device__ ull   g_W1f[16 * 2 * 2 * 32];   // B1 frags: [j16][t2][term2][lane32]
__device__ ull   g_W2f[8 * 8 * 2 * 32];    // B2 frags: [j8][t8][term2][lane32]

// ---------------------------------------------------------------------------
// helpers
// ---------------------------------------------------------------------------
__device__ __forceinline__ void mma16816(float c[4], const uint32_t a[4],
                                         uint32_t b0, uint32_t b1) {
    asm volatile(
        "mma.sync.aligned.m16n8k16.row.col.f32.bf16.bf16.f32 "
        "{%0,%1,%2,%3},{%4,%5,%6,%7},{%8,%9},{%0,%1,%2,%3};"
        : "+f"(c[0]), "+f"(c[1]), "+f"(c[2]), "+f"(c[3])
        : "r"(a[0]), "r"(a[1]), "r"(a[2]), "r"(a[3]), "r"(b0), "r"(b1));
}

// pack (x -> low half, y -> high half) as bf16x2; also produce residual pack
__device__ __forceinline__ void bfs2(float x, float y, uint32_t& hi, uint32_t& lo) {
    asm("cvt.rn.bf16x2.f32 %0, %1, %2;" : "=r"(hi) : "f"(y), "f"(x));
    float xr = x - __uint_as_float(hi << 16);
    float yr = y - __uint_as_float(hi & 0xFFFF0000u);
    asm("cvt.rn.bf16x2.f32 %0, %1, %2;" : "=r"(lo) : "f"(yr), "f"(xr));
}

// fp32x2 helpers for node-side kernels
__device__ __forceinline__ ull dup2(float x) { ull r; asm("mov.b64 %0,{%1,%1};" : "=l"(r) : "f"(x)); return r; }
__device__ __forceinline__ float2 up2(ull v) { float2 r; asm("mov.b64 {%0,%1},%2;" : "=f"(r.x), "=f"(r.y) : "l"(v)); return r; }
__device__ __forceinline__ ull fma2(ull a, ull b, ull c) { ull d; asm("fma.rn.f32x2 %0,%1,%2,%3;" : "=l"(d) : "l"(a), "l"(b), "l"(c)); return d; }

// ---------------------------------------------------------------------------
// zero kernel: d_out and g_deg
// ---------------------------------------------------------------------------
__global__ void zero_kernel(float* __restrict__ out) {
    int i = blockIdx.x * blockDim.x + threadIdx.x;
    if (i < NN * 64) out[i] = 0.0f;
    if (i < NN) g_deg[i] = 0.0f;
}

// ---------------------------------------------------------------------------
// Weight fragment prep (bf16 hi/lo split, mma B-fragment order)
// ---------------------------------------------------------------------------
__global__ void prep_frags(const float* __restrict__ W1, const float* __restrict__ W2) {
    int idx = blockIdx.x * blockDim.x + threadIdx.x;
    if (idx < 2048) {                        // W1c frags
        int lane = idx & 31, fragid = idx >> 5;
        int term = fragid & 1, t = (fragid >> 1) & 1, j = fragid >> 2;
        int n = j * 8 + (lane >> 2);
        int k0 = t * 16 + (lane & 3) * 2;
        float v00 = W1[(size_t)(128 + k0) * 128 + n];
        float v01 = W1[(size_t)(128 + k0 + 1) * 128 + n];
        float v10 = W1[(size_t)(128 + k0 + 8) * 128 + n];
        float v11 = W1[(size_t)(128 + k0 + 9) * 128 + n];
        uint32_t h0, l0, h1, l1;
        bfs2(v00, v01, h0, l0);
        bfs2(v10, v11, h1, l1);
        g_W1f[idx] = term ? (((ull)l1 << 32) | l0) : (((ull)h1 << 32) | h0);
    }
    if (idx < 4096) {                        // W2 frags
        int lane = idx & 31, fragid = idx >> 5;
        int term = fragid & 1, t = (fragid >> 1) & 7, j = fragid >> 4;
        int n = j * 8 + (lane >> 2);
        int k0 = t * 16 + (lane & 3) * 2;
        float v00 = W2[(size_t)k0 * 64 + n];
        float v01 = W2[(size_t)(k0 + 1) * 64 + n];
        float v10 = W2[(size_t)(k0 + 8) * 64 + n];
        float v11 = W2[(size_t)(k0 + 9) * 64 + n];
        uint32_t h0, l0, h1, l1;
        bfs2(v00, v01, h0, l0);
        bfs2(v10, v11, h1, l1);
        g_W2f[idx] = term ? (((ull)l1 << 32) | l0) : (((ull)h1 << 32) | h0);
    }
}

// ---------------------------------------------------------------------------
// Fused S|R precompute (proven): g_SR = nodes @ [W1a|W1b] (+b1 on S half)
// ---------------------------------------------------------------------------
__global__ void __launch_bounds__(256) sr_gemm_kernel(
    const float* __restrict__ A, const float* __restrict__ W1,
    const float* __restrict__ b1, int M)
{
    extern __shared__ float sm[];
    float* sAT = sm;               // [64][68]
    float* sB  = sm + 64 * 68;     // [64][256]
    const int tid = threadIdx.x;
    const int n0  = blockIdx.x * 64;

#pragma unroll
    for (int j = 0; j < 4; j++) {
        int s = tid + j * 256;
        int row = s >> 4, k0 = (s & 15) << 2, gn = n0 + row;
        float4 v = make_float4(0.f, 0.f, 0.f, 0.f);
        if (gn < M) v = *(const float4*)(A + (size_t)gn * 64 + k0);
        sAT[(k0 + 0) * 68 + row] = v.x; sAT[(k0 + 1) * 68 + row] = v.y;
        sAT[(k0 + 2) * 68 + row] = v.z; sAT[(k0 + 3) * 68 + row] = v.w;
    }
#pragma unroll
    for (int j = 0; j < 16; j++) {
        int s = tid + j * 256;
        int r = s >> 6, c4 = (s & 63) * 4;
        const float* src = (c4 < 128) ? (W1 + (size_t)r * 128 + c4)
                                      : (W1 + (size_t)(64 + r) * 128 + (c4 - 128));
        *(float4*)(sB + r * 256 + c4) = *(const float4*)src;
    }
    __syncthreads();

    const int ty = tid >> 4, tx = tid & 15;
    ull acc[4][4][2];
#pragma unroll
    for (int m = 0; m < 4; m++)
#pragma unroll
        for (int q = 0; q < 4; q++) { acc[m][q][0] = 0ull; acc[m][q][1] = 0ull; }

#pragma unroll 8
    for (int k = 0; k < 64; k++) {
        float4 a = *(const float4*)(sAT + k * 68 + ty * 4);
        ull aa[4] = {dup2(a.x), dup2(a.y), dup2(a.z), dup2(a.w)};
#pragma unroll
        for (int q = 0; q < 4; q++) {
            ulonglong2 b = *(const ulonglong2*)(sB + k * 256 + q * 64 + tx * 4);
#pragma unroll
            for (int m = 0; m < 4; m++) {
                acc[m][q][0] = fma2(aa[m], b.x, acc[m][q][0]);
                acc[m][q][1] = fma2(aa[m], b.y, acc[m][q][1]);
            }
        }
    }
    float4 bq[4];
#pragma unroll
    for (int q = 0; q < 4; q++)
        bq[q] = (q < 2) ? *(const float4*)(b1 + q * 64 + tx * 4)
                        : make_float4(0.f, 0.f, 0.f, 0.f);
#pragma unroll
    for (int m = 0; m < 4; m++) {
        int gn = n0 + ty * 4 + m;
        if (gn < M) {
#pragma unroll
            for (int q = 0; q < 4; q++) {
                float2 u0 = up2(acc[m][q][0]), u1 = up2(acc[m][q][1]);
                *(float4*)(g_SR + (size_t)gn * 256 + q * 64 + tx * 4) =
                    make_float4(u0.x + bq[q].x, u0.y + bq[q].y, u1.x + bq[q].z, u1.y + bq[q].w);
            }
        }
    }
}

// ---------------------------------------------------------------------------
// Final kernel: out = out_agg * 1/max(deg,1) + nodes @ Wn + bn
// ---------------------------------------------------------------------------
__global__ void __launch_bounds__(256) final_kernel(
    const float* __restrict__ A, const float* __restrict__ B,
    const float* __restrict__ bias, float* __restrict__ C, int M)
{
    extern __shared__ float sm[];
    float* sAT = sm;
    float* sB  = sm + 64 * 68;
    const int tid = threadIdx.x;
    const int n0  = blockIdx.x * 64;

#pragma unroll
    for (int j = 0; j < 4; j++) {
        int s = tid + j * 256;
        int row = s >> 4, k0 = (s & 15) << 2, gn = n0 + row;
        float4 v = make_float4(0.f, 0.f, 0.f, 0.f);
        if (gn < M) v = *(const float4*)(A + (size_t)gn * 64 + k0);
        sAT[(k0 + 0) * 68 + row] = v.x; sAT[(k0 + 1) * 68 + row] = v.y;
        sAT[(k0 + 2) * 68 + row] = v.z; sAT[(k0 + 3) * 68 + row] = v.w;
    }
#pragma unroll
    for (int j = 0; j < 4; j++) {
        int s = tid + j * 256;
        ((float4*)sB)[s] = ((const float4*)B)[s];
    }
    __syncthreads();

    const int ty = tid >> 4, tx = tid & 15;
    ull acc[4][2];
#pragma unroll
    for (int m = 0; m < 4; m++) { acc[m][0] = 0ull; acc[m][1] = 0ull; }
#pragma unroll 8
    for (int k = 0; k < 64; k++) {
        float4 a = *(const float4*)(sAT + k * 68 + ty * 4);
        ulonglong2 b = *(const ulonglong2*)(sB + k * 64 + tx * 4);
        ull aa[4] = {dup2(a.x), dup2(a.y), dup2(a.z), dup2(a.w)};
#pragma unroll
        for (int m = 0; m < 4; m++) {
            acc[m][0] = fma2(aa[m], b.x, acc[m][0]);
            acc[m][1] = fma2(aa[m], b.y, acc[m][1]);
        }
    }
    float4 bb = *(const float4*)(bias + tx * 4);
#pragma unroll
    for (int m = 0; m < 4; m++) {
        int gn = n0 + ty * 4 + m;
        if (gn < M) {
            float inv = 1.0f / fmaxf(g_deg[gn], 1.0f);
            float4 ag = *(const float4*)(C + (size_t)gn * 64 + tx * 4);
            float2 u0 = up2(acc[m][0]), u1 = up2(acc[m][1]);
            *(float4*)(C + (size_t)gn * 64 + tx * 4) =
                make_float4(ag.x * inv + u0.x + bb.x, ag.y * inv + u0.y + bb.y,
                            ag.z * inv + u1.x + bb.z, ag.w * inv + u1.y + bb.w);
        }
    }
}

// ---------------------------------------------------------------------------
// Edge kernel: persistent warps, mma.sync bf16x3, register-resident fusion.
// R7-proven config: 128 threads, 2 blocks/SM (no register spills).
// Scatters RAW (m+b2) sums; accumulates degree via RED.
// ---------------------------------------------------------------------------
#define N_CHUNKS (NE / 32)

__global__ void __launch_bounds__(128, 2) edge_kernel(
    const float* __restrict__ edges,
    const int*   __restrict__ senders,
    const int*   __restrict__ receivers,
    const float* __restrict__ b2,
    float*       __restrict__ out)
{
    extern __shared__ char smem[];
    ull*   sW1f = (ull*)smem;
    ull*   sW2f = (ull*)(smem + 16384);
    float* sE   = (float*)(smem + 49152);

    const int tid  = threadIdx.x;
    const int w    = tid >> 5;
    const int lane = tid & 31;

    // stage weight fragments once per block
#pragma unroll
    for (int j = 0; j < 16; j++) sW1f[tid + j * 128] = g_W1f[tid + j * 128];
#pragma unroll
    for (int j = 0; j < 32; j++) sW2f[tid + j * 128] = g_W2f[tid + j * 128];
    __syncthreads();

    float* myE = sE + w * 32 * 36;
    const int gw     = blockIdx.x * 4 + w;
    const int stride = gridDim.x * 4;

    const int r   = lane >> 2;          // 0..7
    const int c2x = (lane & 3) * 2;     // 0,2,4,6
    const int pb  = (lane >> 1) & 1;    // pair base selector
    const bool oddl = lane & 1;

    for (int chunk = gw; chunk < N_CHUNKS; chunk += stride) {
        const int e0 = chunk * 32;
        __syncwarp();
#pragma unroll
        for (int q = 0; q < 8; q++) {
            int row = q * 4 + (lane >> 3);
            int col = (lane & 7) * 4;
            *(float4*)(myE + row * 36 + col) =
                *(const float4*)(edges + (size_t)(e0 + row) * 32 + col);
        }
        const int snd = senders[e0 + lane];
        const int rcv = receivers[e0 + lane];
        atomicAdd(&g_deg[rcv], 1.0f);       // no return use -> RED
        __syncwarp();

#pragma unroll
        for (int mt = 0; mt < 2; mt++) {
            const int mb = mt * 16;

            // ---- A1 fragments (edge feats, hi/lo split) ----
            uint32_t a1h[2][4], a1l[2][4];
#pragma unroll
            for (int t = 0; t < 2; t++) {
                float2 x0 = *(const float2*)(myE + (mb + r) * 36 + t * 16 + c2x);
                float2 x1 = *(const float2*)(myE + (mb + r + 8) * 36 + t * 16 + c2x);
                float2 x2 = *(const float2*)(myE + (mb + r) * 36 + t * 16 + c2x + 8);
                float2 x3 = *(const float2*)(myE + (mb + r + 8) * 36 + t * 16 + c2x + 8);
                bfs2(x0.x, x0.y, a1h[t][0], a1l[t][0]);
                bfs2(x1.x, x1.y, a1h[t][1], a1l[t][1]);
                bfs2(x2.x, x2.y, a1h[t][2], a1l[t][2]);
                bfs2(x3.x, x3.y, a1h[t][3], a1l[t][3]);
            }

            const int s_r  = __shfl_sync(0xFFFFFFFFu, snd, mb + r);
            const int s_r8 = __shfl_sync(0xFFFFFFFFu, snd, mb + r + 8);
            const int r_r  = __shfl_sync(0xFFFFFFFFu, rcv, mb + r);
            const int r_r8 = __shfl_sync(0xFFFFFFFFu, rcv, mb + r + 8);
            const float* Sr  = g_SR + (size_t)s_r  * 256;
            const float* Sr8 = g_SR + (size_t)s_r8 * 256;
            const float* Rr  = g_SR + (size_t)r_r  * 256 + 128;
            const float* Rr8 = g_SR + (size_t)r_r8 * 256 + 128;

            // ---- GEMM1 + epilogue1 -> A2 frags ----
            uint32_t a2h[8][4], a2l[8][4];
#pragma unroll
            for (int t2 = 0; t2 < 8; t2++) {
                float c1[2][4] = {{0.f, 0.f, 0.f, 0.f}, {0.f, 0.f, 0.f, 0.f}};
#pragma unroll
                for (int half = 0; half < 2; half++) {
                    int j = t2 * 2 + half;
#pragma unroll
                    for (int t = 0; t < 2; t++) {
                        ull bh = sW1f[((j * 2 + t) * 2 + 0) * 32 + lane];
                        ull bl = sW1f[((j * 2 + t) * 2 + 1) * 32 + lane];
                        uint32_t bh0 = (uint32_t)bh, bh1 = (uint32_t)(bh >> 32);
                        uint32_t bl0 = (uint32_t)bl, bl1 = (uint32_t)(bl >> 32);
                        mma16816(c1[half], a1h[t], bh0, bh1);
                        mma16816(c1[half], a1h[t], bl0, bl1);
                        mma16816(c1[half], a1l[t], bh0, bh1);
                    }
                }
#pragma unroll
                for (int half = 0; half < 2; half++) {
                    int j = t2 * 2 + half;
                    float2 sv0 = *(const float2*)(Sr  + j * 8 + c2x);
                    float2 sv1 = *(const float2*)(Sr8 + j * 8 + c2x);
                    float2 rv0 = *(const float2*)(Rr  + j * 8 + c2x);
                    float2 rv1 = *(const float2*)(Rr8 + j * 8 + c2x);
                    float h0 = fmaxf(c1[half][0] + sv0.x + rv0.x, 0.f);
                    float h1 = fmaxf(c1[half][1] + sv0.y + rv0.y, 0.f);
                    float h2 = fmaxf(c1[half][2] + sv1.x + rv1.x, 0.f);
                    float h3 = fmaxf(c1[half][3] + sv1.y + rv1.y, 0.f);
                    bfs2(h0, h1, a2h[t2][half * 2 + 0], a2l[t2][half * 2 + 0]);
                    bfs2(h2, h3, a2h[t2][half * 2 + 1], a2l[t2][half * 2 + 1]);
                }
            }

            const int er = oddl ? r_r8 : r_r;
            float* outp = out + (size_t)er * 64 + pb * 4;

            // ---- GEMM2 per n-tile + raw scatter ----
#pragma unroll
            for (int j = 0; j < 8; j++) {
                float c2[4] = {0.f, 0.f, 0.f, 0.f};
#pragma unroll
                for (int t = 0; t < 8; t++) {
                    ull bh = sW2f[((j * 8 + t) * 2 + 0) * 32 + lane];
                    ull bl = sW2f[((j * 8 + t) * 2 + 1) * 32 + lane];
                    uint32_t bh0 = (uint32_t)bh, bh1 = (uint32_t)(bh >> 32);
                    uint32_t bl0 = (uint32_t)bl, bl1 = (uint32_t)(bl >> 32);
                    mma16816(c2, a2h[t], bh0, bh1);
                    mma16816(c2, a2h[t], bl0, bl1);
                    mma16816(c2, a2l[t], bh0, bh1);
                }
                float x0 = __shfl_xor_sync(0xFFFFFFFFu, c2[0], 1);
                float x1 = __shfl_xor_sync(0xFFFFFFFFu, c2[1], 1);
                float x2 = __shfl_xor_sync(0xFFFFFFFFu, c2[2], 1);
                float x3 = __shfl_xor_sync(0xFFFFFFFFu, c2[3], 1);
                float v0, v1, v2, v3;
                if (!oddl) { v0 = c2[0]; v1 = c2[1]; v2 = x0; v3 = x1; }
                else       { v0 = x2;    v1 = x3;    v2 = c2[2]; v3 = c2[3]; }
                float4 bb = *(const float4*)(b2 + j * 8 + pb * 4);
                v0 += bb.x;  v1 += bb.y;  v2 += bb.z;  v3 += bb.w;
                asm volatile("red.global.add.v4.f32 [%0], {%1,%2,%3,%4};"
                             :: "l"(outp + j * 8), "f"(v0), "f"(v1), "f"(v2), "f"(v3)
                             : "memory");
            }
        }
    }
}

// ---------------------------------------------------------------------------
// Launch
// ---------------------------------------------------------------------------
extern "C" void kernel_launch(void* const* d_in, const int* in_sizes, int n_in,
                              void* d_out, int out_size)
{
    const float* nodes     = (const float*)d_in[0];
    const float* edges     = (const float*)d_in[1];
    const int*   senders   = (const int*)d_in[2];
    const int*   receivers = (const int*)d_in[3];
    const float* W1        = (const float*)d_in[4];
    const float* b1        = (const float*)d_in[5];
    const float* W2        = (const float*)d_in[6];
    const float* b2        = (const float*)d_in[7];
    const float* Wn        = (const float*)d_in[8];
    const float* bn        = (const float*)d_in[9];
    float* out = (float*)d_out;

    const size_t sm_sr    = (64 * 68 + 64 * 256) * sizeof(float);
    const size_t sm_small = (64 * 68 + 64 * 64) * sizeof(float);
    const size_t sm_edge  = 16384 + 32768 + 4 * 32 * 36 * sizeof(float);  // 67,584

    cudaFuncSetAttribute(sr_gemm_kernel,
                         cudaFuncAttributeMaxDynamicSharedMemorySize, (int)sm_sr);
    cudaFuncSetAttribute(edge_kernel,
                         cudaFuncAttributeMaxDynamicSharedMemorySize, (int)sm_edge);

    zero_kernel<<<(NN * 64 + 255) / 256, 256>>>(out);
    prep_frags<<<16, 256>>>(W1, W2);

    int gnodes = (NN + 63) / 64;
    sr_gemm_kernel<<<gnodes, 256, sm_sr>>>(nodes, W1, b1, NN);

    edge_kernel<<<304, 128, sm_edge>>>(edges, senders, receivers, b2, out);

    final_kernel<<<gnodes, 256, sm_small>>>(nodes, Wn, bn, out, NN);
}